// round 1
// baseline (speedup 1.0000x reference)
#include <cuda_runtime.h>
#include <math.h>

// Problem constants
#define N_TOK   4096
#define D_MODEL 1024
#define HEADS   16
#define DH      64
#define QKV_COLS 3072   // 3 * inner, inner = HEADS*DH = 1024

// Scratch (allocation-free rule: __device__ globals)
__device__ float g_h[N_TOK * D_MODEL];       // LayerNorm output       (16 MB)
__device__ float g_qkv[N_TOK * QKV_COLS];    // QKV projection / RoPE'd (48 MB)
__device__ float g_attn[N_TOK * D_MODEL];    // attention output       (16 MB)

// ---------------------------------------------------------------------------
// LayerNorm: one block per row (1024 elems, 256 threads)
// ---------------------------------------------------------------------------
__global__ void ln_kernel(const float* __restrict__ x,
                          const float* __restrict__ g,
                          const float* __restrict__ b) {
    int row = blockIdx.x;
    const float* xr = x + (size_t)row * D_MODEL;
    float s = 0.f, s2 = 0.f;
    for (int i = threadIdx.x; i < D_MODEL; i += 256) {
        float v = xr[i];
        s += v; s2 += v * v;
    }
    #pragma unroll
    for (int o = 16; o; o >>= 1) {
        s  += __shfl_xor_sync(0xffffffffu, s,  o);
        s2 += __shfl_xor_sync(0xffffffffu, s2, o);
    }
    __shared__ float ws[8], ws2[8];
    __shared__ float mu_s, inv_s;
    int wid = threadIdx.x >> 5, lane = threadIdx.x & 31;
    if (lane == 0) { ws[wid] = s; ws2[wid] = s2; }
    __syncthreads();
    if (threadIdx.x == 0) {
        float S = 0.f, S2 = 0.f;
        #pragma unroll
        for (int i = 0; i < 8; i++) { S += ws[i]; S2 += ws2[i]; }
        float mu  = S  * (1.f / D_MODEL);
        float var = S2 * (1.f / D_MODEL) - mu * mu;
        mu_s  = mu;
        inv_s = rsqrtf(var + 1e-5f);
    }
    __syncthreads();
    float mu = mu_s, inv = inv_s;
    float* yr = g_h + (size_t)row * D_MODEL;
    for (int i = threadIdx.x; i < D_MODEL; i += 256)
        yr[i] = (xr[i] - mu) * inv * g[i] + b[i];
}

// ---------------------------------------------------------------------------
// Tiled fp32 GEMM: C[M,N] = A[M,K] @ B[K,N]. BM=BN=64, BK=16, 256 threads,
// 4x4 register micro-tile per thread (cols strided by 16 for bank spread).
// M, N, K all multiples of 64/16 here — no bounds checks.
// ---------------------------------------------------------------------------
__global__ void gemm64(const float* __restrict__ A, const float* __restrict__ B,
                       float* __restrict__ C, int M, int N, int K) {
    __shared__ float As[16][64];
    __shared__ float Bs[16][64];
    int bm = blockIdx.y * 64, bn = blockIdx.x * 64;
    int tid = threadIdx.x;
    int r0 = (tid >> 4) << 2;     // row base  (0..60)
    int c0 = tid & 15;            // col base; cols are c0 + 16*j
    int arow = tid >> 2, acol = (tid & 3) << 2;
    int brow = tid >> 4, bcol = (tid & 15) << 2;

    float acc[4][4] = {};
    for (int k0 = 0; k0 < K; k0 += 16) {
        float4 av = *(const float4*)(A + (size_t)(bm + arow) * K + k0 + acol);
        As[acol + 0][arow] = av.x;
        As[acol + 1][arow] = av.y;
        As[acol + 2][arow] = av.z;
        As[acol + 3][arow] = av.w;
        float4 bv = *(const float4*)(B + (size_t)(k0 + brow) * N + bn + bcol);
        *(float4*)&Bs[brow][bcol] = bv;
        __syncthreads();
        #pragma unroll
        for (int k = 0; k < 16; k++) {
            float ar[4], br[4];
            #pragma unroll
            for (int i = 0; i < 4; i++) ar[i] = As[k][r0 + i];
            #pragma unroll
            for (int j = 0; j < 4; j++) br[j] = Bs[k][c0 + 16 * j];
            #pragma unroll
            for (int i = 0; i < 4; i++)
                #pragma unroll
                for (int j = 0; j < 4; j++) acc[i][j] += ar[i] * br[j];
        }
        __syncthreads();
    }
    #pragma unroll
    for (int i = 0; i < 4; i++)
        #pragma unroll
        for (int j = 0; j < 4; j++)
            C[(size_t)(bm + r0 + i) * N + bn + c0 + 16 * j] = acc[i][j];
}

// ---------------------------------------------------------------------------
// Copy PRE-RoPE k, v into output cache slots: out[inner*N + ...] layout
// [2][H][N][DH] appended after the 4.19M-element attention output.
// ---------------------------------------------------------------------------
__global__ void copy_kv_kernel(float* __restrict__ out) {
    int idx = blockIdx.x * blockDim.x + threadIdx.x;
    const int TOT = 2 * HEADS * N_TOK * DH;
    if (idx >= TOT) return;
    int which = idx / (HEADS * N_TOK * DH);          // 0 = k, 1 = v
    int r   = idx - which * (HEADS * N_TOK * DH);
    int h   = r / (N_TOK * DH);
    int rem = r - h * (N_TOK * DH);
    int n   = rem / DH;
    int d   = rem - n * DH;
    out[(size_t)N_TOK * D_MODEL + idx] =
        g_qkv[(size_t)n * QKV_COLS + D_MODEL + which * D_MODEL + h * DH + d];
}

// ---------------------------------------------------------------------------
// Interleaved-pair RoPE, applied in-place to q (cols 0..1023) and k (1024..2047)
// ---------------------------------------------------------------------------
__global__ void rope_kernel() {
    int idx = blockIdx.x * blockDim.x + threadIdx.x;
    if (idx >= N_TOK * 1024) return;       // 4096 rows * (512 q-pairs + 512 k-pairs)
    int n    = idx >> 10;
    int rem  = idx & 1023;
    int mat  = rem >> 9;                   // 0 = q, 1 = k
    int pair = rem & 511;
    int h  = pair >> 5;
    int pd = pair & 31;                    // pair index within head; d = 2*pd
    // inv_freq = 10000^(-(2*pd)/64)
    float inv = exp2f(-((float)(2 * pd) * (1.f / 64.f)) * 13.287712379549449f);
    float ang = (float)n * inv;
    float sn, cs;
    sincosf(ang, &sn, &cs);                // accurate range reduction (ang up to 4096)
    float* base = g_qkv + (size_t)n * QKV_COLS + mat * D_MODEL + h * DH + 2 * pd;
    float x0 = base[0], x1 = base[1];
    base[0] = x0 * cs - x1 * sn;
    base[1] = x1 * cs + x0 * sn;
}

// ---------------------------------------------------------------------------
// Causal flash attention. Grid (64 q-tiles, 16 heads), 256 threads.
// BM=BN=64, DH=64. Smem: Q(64x65) K(64x65, reused for P) V(64x65) = 49920 B.
// Thread owns rows r0..r0+3 (r0=(tid/16)*4) and cols/dims {c0+16j} (c0=tid%16).
// Online softmax; row reductions via 16-lane shuffle groups.
// ---------------------------------------------------------------------------
__global__ void flash_kernel(float* __restrict__ outdummy) {
    extern __shared__ float sm[];
    float* q_s = sm;
    float* k_s = sm + 64 * 65;   // also holds P after scores are consumed
    float* v_s = sm + 2 * 64 * 65;

    int qt = blockIdx.x, h = blockIdx.y;
    int i0 = qt * 64;
    int tid = threadIdx.x;
    int r0 = (tid >> 4) << 2;
    int c0 = tid & 15;

    // Load Q tile (pre-scaled by 1/sqrt(DH) = 0.125)
    const float* qbase = g_qkv + (size_t)i0 * QKV_COLS + h * DH;
    for (int e = tid; e < 64 * 16; e += 256) {
        int row = e >> 4, col = (e & 15) << 2;
        float4 v = *(const float4*)(qbase + (size_t)row * QKV_COLS + col);
        float* d = q_s + row * 65 + col;
        d[0] = v.x * 0.125f; d[1] = v.y * 0.125f;
        d[2] = v.z * 0.125f; d[3] = v.w * 0.125f;
    }

    float acc[4][4] = {};
    float m[4], l[4] = {};
    #pragma unroll
    for (int i = 0; i < 4; i++) m[i] = -1e30f;

    for (int kt = 0; kt <= qt; kt++) {
        __syncthreads();   // prior P/V reads done (also orders Q load on iter 0)
        const float* kb = g_qkv + (size_t)(kt * 64) * QKV_COLS + D_MODEL + h * DH;
        const float* vb = kb + D_MODEL;
        for (int e = tid; e < 64 * 16; e += 256) {
            int row = e >> 4, col = (e & 15) << 2;
            float4 kv = *(const float4*)(kb + (size_t)row * QKV_COLS + col);
            float4 vv = *(const float4*)(vb + (size_t)row * QKV_COLS + col);
            float* dk = k_s + row * 65 + col;
            dk[0] = kv.x; dk[1] = kv.y; dk[2] = kv.z; dk[3] = kv.w;
            float* dv = v_s + row * 65 + col;
            dv[0] = vv.x; dv[1] = vv.y; dv[2] = vv.z; dv[3] = vv.w;
        }
        __syncthreads();

        // S = Q K^T (4x4 per thread)
        float s[4][4] = {};
        #pragma unroll 8
        for (int k = 0; k < 64; k++) {
            float ar[4], br[4];
            #pragma unroll
            for (int i = 0; i < 4; i++) ar[i] = q_s[(r0 + i) * 65 + k];
            #pragma unroll
            for (int j = 0; j < 4; j++) br[j] = k_s[(c0 + 16 * j) * 65 + k];
            #pragma unroll
            for (int i = 0; i < 4; i++)
                #pragma unroll
                for (int j = 0; j < 4; j++) s[i][j] += ar[i] * br[j];
        }

        // Causal mask (only the diagonal tile needs it; i0 == j0 there)
        if (kt == qt) {
            #pragma unroll
            for (int i = 0; i < 4; i++)
                #pragma unroll
                for (int j = 0; j < 4; j++)
                    if (c0 + 16 * j > r0 + i) s[i][j] = -1e30f;
        }

        // Row max across this tile (16-lane groups share the same 4 rows)
        float mloc[4], rs[4];
        #pragma unroll
        for (int i = 0; i < 4; i++)
            mloc[i] = fmaxf(fmaxf(s[i][0], s[i][1]), fmaxf(s[i][2], s[i][3]));
        #pragma unroll
        for (int o = 1; o < 16; o <<= 1)
            #pragma unroll
            for (int i = 0; i < 4; i++)
                mloc[i] = fmaxf(mloc[i], __shfl_xor_sync(0xffffffffu, mloc[i], o));

        #pragma unroll
        for (int i = 0; i < 4; i++) {
            float mn = fmaxf(m[i], mloc[i]);
            float corr = __expf(m[i] - mn);
            l[i] *= corr;
            #pragma unroll
            for (int j = 0; j < 4; j++) acc[i][j] *= corr;
            float r = 0.f;
            #pragma unroll
            for (int j = 0; j < 4; j++) {
                s[i][j] = __expf(s[i][j] - mn);
                r += s[i][j];
            }
            rs[i] = r;
            m[i] = mn;
        }
        #pragma unroll
        for (int o = 1; o < 16; o <<= 1)
            #pragma unroll
            for (int i = 0; i < 4; i++)
                rs[i] += __shfl_xor_sync(0xffffffffu, rs[i], o);
        #pragma unroll
        for (int i = 0; i < 4; i++) l[i] += rs[i];

        __syncthreads();   // everyone done reading k_s (scores computed)
        // Stash P into k_s
        #pragma unroll
        for (int i = 0; i < 4; i++)
            #pragma unroll
            for (int j = 0; j < 4; j++)
                k_s[(r0 + i) * 65 + c0 + 16 * j] = s[i][j];
        __syncthreads();

        // O += P @ V   (acc columns now index dims: d = c0 + 16*dd)
        for (int j = 0; j < 64; j++) {
            float vv[4];
            #pragma unroll
            for (int d = 0; d < 4; d++) vv[d] = v_s[j * 65 + c0 + 16 * d];
            #pragma unroll
            for (int i = 0; i < 4; i++) {
                float p = k_s[(r0 + i) * 65 + j];
                #pragma unroll
                for (int d = 0; d < 4; d++) acc[i][d] += p * vv[d];
            }
        }
    }

    // Epilogue: normalize and write [n, h*DH + d]
    #pragma unroll
    for (int i = 0; i < 4; i++) {
        float invl = 1.f / l[i];
        float* ob = g_attn + (size_t)(i0 + r0 + i) * D_MODEL + h * DH;
        #pragma unroll
        for (int d = 0; d < 4; d++)
            ob[c0 + 16 * d] = acc[i][d] * invl;
    }
    (void)outdummy;
}

// ---------------------------------------------------------------------------
// kernel_launch: LN -> QKV GEMM -> KV cache copy (pre-RoPE) -> RoPE ->
// flash attention -> out projection. All on default stream, graph-capturable.
// Output layout: [out (4096x1024) | new_k (16x4096x64) | new_v (16x4096x64)]
// ---------------------------------------------------------------------------
extern "C" void kernel_launch(void* const* d_in, const int* in_sizes, int n_in,
                              void* d_out, int out_size) {
    const float* x     = (const float*)d_in[0];
    const float* w_qkv = (const float*)d_in[1];
    const float* w_out = (const float*)d_in[2];
    const float* ln_g  = (const float*)d_in[3];
    const float* ln_b  = (const float*)d_in[4];
    float* out = (float*)d_out;

    float *p_h, *p_qkv, *p_attn;
    cudaGetSymbolAddress((void**)&p_h,    g_h);
    cudaGetSymbolAddress((void**)&p_qkv,  g_qkv);
    cudaGetSymbolAddress((void**)&p_attn, g_attn);

    // 1. LayerNorm
    ln_kernel<<<N_TOK, 256>>>(x, ln_g, ln_b);

    // 2. QKV projection: [4096,1024] @ [1024,3072]
    gemm64<<<dim3(QKV_COLS / 64, N_TOK / 64), 256>>>(p_h, w_qkv, p_qkv,
                                                     N_TOK, QKV_COLS, D_MODEL);

    // 3. Cache copies (pre-RoPE k, v)
    {
        int tot = 2 * HEADS * N_TOK * DH;
        copy_kv_kernel<<<(tot + 255) / 256, 256>>>(out);
    }

    // 4. RoPE on q and k (in place)
    {
        int tot = N_TOK * 1024;
        rope_kernel<<<(tot + 255) / 256, 256>>>();
    }

    // 5. Causal flash attention
    {
        static const int SMEM = 3 * 64 * 65 * (int)sizeof(float); // 49920 B
        cudaFuncSetAttribute(flash_kernel,
                             cudaFuncAttributeMaxDynamicSharedMemorySize, SMEM);
        flash_kernel<<<dim3(N_TOK / 64, HEADS), 256, SMEM>>>(out);
    }

    // 6. Output projection: [4096,1024] @ [1024,1024] -> out[0 .. 4194304)
    gemm64<<<dim3(D_MODEL / 64, N_TOK / 64), 256>>>(p_attn, w_out, out,
                                                    N_TOK, D_MODEL, D_MODEL);
    (void)in_sizes; (void)n_in; (void)out_size;
}

// round 2
// speedup vs baseline: 1.2117x; 1.2117x over previous
#include <cuda_runtime.h>
#include <math.h>

// Problem constants
#define N_TOK   4096
#define D_MODEL 1024
#define HEADS   16
#define DH      64
#define QKV_COLS 3072   // 3 * inner, inner = HEADS*DH = 1024

typedef unsigned long long u64;

// ---- packed fp32x2 helpers (SASS FFMA2 path, PTX-only) ----------------------
__device__ __forceinline__ u64 dup2(float a) {
    u64 d; asm("mov.b64 %0, {%1, %1};" : "=l"(d) : "f"(a)); return d;
}
__device__ __forceinline__ u64 pack2(float lo, float hi) {
    u64 d; asm("mov.b64 %0, {%1, %2};" : "=l"(d) : "f"(lo), "f"(hi)); return d;
}
__device__ __forceinline__ void fma2(u64& d, u64 a, u64 b) {
    asm("fma.rn.f32x2 %0, %1, %2, %0;" : "+l"(d) : "l"(a), "l"(b));
}
__device__ __forceinline__ void mul2(u64& d, u64 a) {
    asm("mul.rn.f32x2 %0, %0, %1;" : "+l"(d) : "l"(a));
}
__device__ __forceinline__ float lo2(u64 v) { return __uint_as_float((unsigned)v); }
__device__ __forceinline__ float hi2(u64 v) { return __uint_as_float((unsigned)(v >> 32)); }

// Scratch (allocation-free rule: __device__ globals)
__device__ float g_h[N_TOK * D_MODEL];       // LayerNorm output       (16 MB)
__device__ float g_qkv[N_TOK * QKV_COLS];    // QKV projection / RoPE'd (48 MB)
__device__ float g_attn[N_TOK * D_MODEL];    // attention output       (16 MB)

// ---------------------------------------------------------------------------
// LayerNorm: one block per row (1024 elems, 256 threads)
// ---------------------------------------------------------------------------
__global__ void ln_kernel(const float* __restrict__ x,
                          const float* __restrict__ g,
                          const float* __restrict__ b) {
    int row = blockIdx.x;
    const float* xr = x + (size_t)row * D_MODEL;
    float s = 0.f, s2 = 0.f;
    for (int i = threadIdx.x; i < D_MODEL; i += 256) {
        float v = xr[i];
        s += v; s2 += v * v;
    }
    #pragma unroll
    for (int o = 16; o; o >>= 1) {
        s  += __shfl_xor_sync(0xffffffffu, s,  o);
        s2 += __shfl_xor_sync(0xffffffffu, s2, o);
    }
    __shared__ float ws[8], ws2[8];
    __shared__ float mu_s, inv_s;
    int wid = threadIdx.x >> 5, lane = threadIdx.x & 31;
    if (lane == 0) { ws[wid] = s; ws2[wid] = s2; }
    __syncthreads();
    if (threadIdx.x == 0) {
        float S = 0.f, S2 = 0.f;
        #pragma unroll
        for (int i = 0; i < 8; i++) { S += ws[i]; S2 += ws2[i]; }
        float mu  = S  * (1.f / D_MODEL);
        float var = S2 * (1.f / D_MODEL) - mu * mu;
        mu_s  = mu;
        inv_s = rsqrtf(var + 1e-5f);
    }
    __syncthreads();
    float mu = mu_s, inv = inv_s;
    float* yr = g_h + (size_t)row * D_MODEL;
    for (int i = threadIdx.x; i < D_MODEL; i += 256)
        yr[i] = (xr[i] - mu) * inv * g[i] + b[i];
}

// ---------------------------------------------------------------------------
// FFMA2 GEMM: C[M,N] = A[M,K] @ B[K,N]. BM=BN=128, BK=16, 256 threads,
// 8x8 micro-tile per thread held as 8x4 packed f32x2 accumulators.
// Thread cols: 32*p + 2*tx + {0,1}, p=0..3; rows: ty*8 + i.
// M%128==0, N%128==0, K%16==0 assumed.
// ---------------------------------------------------------------------------
__global__ __launch_bounds__(256, 2)
void gemm128(const float* __restrict__ A, const float* __restrict__ B,
             float* __restrict__ C, int M, int N, int K) {
    __shared__ float As[16][128];   // transposed: As[k][m]
    __shared__ float Bs[16][128];   // Bs[k][n]
    int bm = blockIdx.y * 128, bn = blockIdx.x * 128;
    int tid = threadIdx.x;
    int ty = tid >> 4, tx = tid & 15;
    int arow = tid >> 1, ak = (tid & 1) * 8;
    int brow = tid >> 4, bcol = (tid & 15) * 8;

    const float4* Ap = (const float4*)(A + (size_t)(bm + arow) * K + ak);

    u64 acc[8][4];
    #pragma unroll
    for (int i = 0; i < 8; i++)
        #pragma unroll
        for (int p = 0; p < 4; p++) acc[i][p] = 0ull;

    for (int k0 = 0; k0 < K; k0 += 16) {
        float4 a0 = Ap[0], a1 = Ap[1];
        Ap += 4;  // advance 16 floats
        const float4* Bp = (const float4*)(B + (size_t)(k0 + brow) * N + bn + bcol);
        float4 b0 = Bp[0], b1 = Bp[1];

        As[ak + 0][arow] = a0.x; As[ak + 1][arow] = a0.y;
        As[ak + 2][arow] = a0.z; As[ak + 3][arow] = a0.w;
        As[ak + 4][arow] = a1.x; As[ak + 5][arow] = a1.y;
        As[ak + 6][arow] = a1.z; As[ak + 7][arow] = a1.w;
        *(float4*)&Bs[brow][bcol]     = b0;
        *(float4*)&Bs[brow][bcol + 4] = b1;
        __syncthreads();

        #pragma unroll
        for (int k = 0; k < 16; k++) {
            u64 bv[4];
            #pragma unroll
            for (int p = 0; p < 4; p++)
                bv[p] = *(const u64*)&Bs[k][32 * p + 2 * tx];
            #pragma unroll
            for (int i = 0; i < 8; i++) {
                u64 a2 = dup2(As[k][ty * 8 + i]);
                #pragma unroll
                for (int p = 0; p < 4; p++) fma2(acc[i][p], a2, bv[p]);
            }
        }
        __syncthreads();
    }

    #pragma unroll
    for (int i = 0; i < 8; i++) {
        float* crow = C + (size_t)(bm + ty * 8 + i) * N + bn;
        #pragma unroll
        for (int p = 0; p < 4; p++)
            *(u64*)&crow[32 * p + 2 * tx] = acc[i][p];
    }
}

// ---------------------------------------------------------------------------
// Copy PRE-RoPE k, v into output cache slots: layout [2][H][N][DH] appended
// after the 4.19M-element attention output.
// ---------------------------------------------------------------------------
__global__ void copy_kv_kernel(float* __restrict__ out) {
    int idx = blockIdx.x * blockDim.x + threadIdx.x;
    const int TOT = 2 * HEADS * N_TOK * DH;
    if (idx >= TOT) return;
    int which = idx / (HEADS * N_TOK * DH);          // 0 = k, 1 = v
    int r   = idx - which * (HEADS * N_TOK * DH);
    int h   = r / (N_TOK * DH);
    int rem = r - h * (N_TOK * DH);
    int n   = rem / DH;
    int d   = rem - n * DH;
    out[(size_t)N_TOK * D_MODEL + idx] =
        g_qkv[(size_t)n * QKV_COLS + D_MODEL + which * D_MODEL + h * DH + d];
}

// ---------------------------------------------------------------------------
// Interleaved-pair RoPE, in-place on q (cols 0..1023) and k (1024..2047)
// ---------------------------------------------------------------------------
__global__ void rope_kernel() {
    int idx = blockIdx.x * blockDim.x + threadIdx.x;
    if (idx >= N_TOK * 1024) return;
    int n    = idx >> 10;
    int rem  = idx & 1023;
    int mat  = rem >> 9;                   // 0 = q, 1 = k
    int pair = rem & 511;
    int h  = pair >> 5;
    int pd = pair & 31;
    float inv = exp2f(-((float)(2 * pd) * (1.f / 64.f)) * 13.287712379549449f);
    float ang = (float)n * inv;
    float sn, cs;
    sincosf(ang, &sn, &cs);
    float* base = g_qkv + (size_t)n * QKV_COLS + mat * D_MODEL + h * DH + 2 * pd;
    float x0 = base[0], x1 = base[1];
    base[0] = x0 * cs - x1 * sn;
    base[1] = x1 * cs + x0 * sn;
}

// ---------------------------------------------------------------------------
// Causal flash attention, FFMA2 inner loops. Grid (64 q-tiles reversed, 16
// heads), 256 threads. Q,K stored transposed in smem so the n/d operand pairs
// are contiguous (LDS.64). Thread owns rows r0..r0+3 (r0=(tid>>4)*4) and
// cols {32p + 2tx + q}. P overwrites k_s.
// ---------------------------------------------------------------------------
#define QS 66   // q_s stride (transposed [d][m])
#define KS 66   // k_s stride (transposed [d][n]; P stored as [m][n] stride 66)
#define VS 68   // v_s stride (row-major [n][d]; 68 keeps float4 alignment)

__global__ __launch_bounds__(256) void flash_kernel() {
    extern __shared__ float sm[];
    float* q_s = sm;
    float* k_s = sm + 64 * QS;
    float* v_s = sm + 64 * QS + 64 * KS;

    int qt = gridDim.x - 1 - blockIdx.x;   // heavy tiles launch first
    int h  = blockIdx.y;
    int i0 = qt * 64;
    int tid = threadIdx.x;
    int ty = tid >> 4, tx = tid & 15;
    int r0 = ty * 4;

    // Load Q tile transposed, pre-scaled by 1/sqrt(DH)
    const float* qbase = g_qkv + (size_t)i0 * QKV_COLS + h * DH;
    for (int e = tid; e < 64 * 16; e += 256) {
        int row = e >> 4, col = (e & 15) << 2;
        float4 v = *(const float4*)(qbase + (size_t)row * QKV_COLS + col);
        q_s[(col + 0) * QS + row] = v.x * 0.125f;
        q_s[(col + 1) * QS + row] = v.y * 0.125f;
        q_s[(col + 2) * QS + row] = v.z * 0.125f;
        q_s[(col + 3) * QS + row] = v.w * 0.125f;
    }

    u64 acc[4][2];
    float m[4], l[4];
    #pragma unroll
    for (int i = 0; i < 4; i++) {
        acc[i][0] = 0ull; acc[i][1] = 0ull;
        m[i] = -1e30f; l[i] = 0.f;
    }

    for (int kt = 0; kt <= qt; kt++) {
        __syncthreads();   // previous P/V reads done (orders Q load on iter 0)
        const float* kb = g_qkv + (size_t)(kt * 64) * QKV_COLS + D_MODEL + h * DH;
        const float* vb = kb + D_MODEL;
        for (int e = tid; e < 64 * 16; e += 256) {
            int row = e >> 4, col = (e & 15) << 2;
            float4 kv = *(const float4*)(kb + (size_t)row * QKV_COLS + col);
            k_s[(col + 0) * KS + row] = kv.x;
            k_s[(col + 1) * KS + row] = kv.y;
            k_s[(col + 2) * KS + row] = kv.z;
            k_s[(col + 3) * KS + row] = kv.w;
            float4 vv = *(const float4*)(vb + (size_t)row * QKV_COLS + col);
            *(float4*)&v_s[row * VS + col] = vv;
        }
        __syncthreads();

        // S = Q K^T, packed pairs over key columns
        u64 s2[4][2];
        #pragma unroll
        for (int i = 0; i < 4; i++) { s2[i][0] = 0ull; s2[i][1] = 0ull; }
        #pragma unroll 4
        for (int k = 0; k < 64; k++) {
            u64 b0 = *(const u64*)&k_s[k * KS + 2 * tx];
            u64 b1 = *(const u64*)&k_s[k * KS + 32 + 2 * tx];
            #pragma unroll
            for (int i = 0; i < 4; i++) {
                u64 a2 = dup2(q_s[k * QS + r0 + i]);
                fma2(s2[i][0], a2, b0);
                fma2(s2[i][1], a2, b1);
            }
        }

        // Unpack: cols j -> {2tx, 2tx+1, 32+2tx, 33+2tx}
        float s[4][4];
        #pragma unroll
        for (int i = 0; i < 4; i++) {
            s[i][0] = lo2(s2[i][0]); s[i][1] = hi2(s2[i][0]);
            s[i][2] = lo2(s2[i][1]); s[i][3] = hi2(s2[i][1]);
        }
        int jc0 = 2 * tx, jc2 = 32 + 2 * tx;

        if (kt == qt) {
            #pragma unroll
            for (int i = 0; i < 4; i++) {
                int row = r0 + i;
                if (jc0     > row) s[i][0] = -1e30f;
                if (jc0 + 1 > row) s[i][1] = -1e30f;
                if (jc2     > row) s[i][2] = -1e30f;
                if (jc2 + 1 > row) s[i][3] = -1e30f;
            }
        }

        // Row max across tile (16-lane groups share the same 4 rows)
        float mloc[4], rs[4];
        #pragma unroll
        for (int i = 0; i < 4; i++)
            mloc[i] = fmaxf(fmaxf(s[i][0], s[i][1]), fmaxf(s[i][2], s[i][3]));
        #pragma unroll
        for (int o = 1; o < 16; o <<= 1)
            #pragma unroll
            for (int i = 0; i < 4; i++)
                mloc[i] = fmaxf(mloc[i], __shfl_xor_sync(0xffffffffu, mloc[i], o));

        #pragma unroll
        for (int i = 0; i < 4; i++) {
            float mn = fmaxf(m[i], mloc[i]);
            float corr = __expf(m[i] - mn);
            l[i] *= corr;
            u64 c2 = dup2(corr);
            mul2(acc[i][0], c2);
            mul2(acc[i][1], c2);
            float r = 0.f;
            #pragma unroll
            for (int j = 0; j < 4; j++) {
                s[i][j] = __expf(s[i][j] - mn);
                r += s[i][j];
            }
            rs[i] = r;
            m[i] = mn;
        }
        #pragma unroll
        for (int o = 1; o < 16; o <<= 1)
            #pragma unroll
            for (int i = 0; i < 4; i++)
                rs[i] += __shfl_xor_sync(0xffffffffu, rs[i], o);
        #pragma unroll
        for (int i = 0; i < 4; i++) l[i] += rs[i];

        __syncthreads();   // everyone done reading k_s
        // Stash P into k_s as [m][n] stride 66 (float2 stores, aligned)
        #pragma unroll
        for (int i = 0; i < 4; i++) {
            *(u64*)&k_s[(r0 + i) * KS + 2 * tx]      = pack2(s[i][0], s[i][1]);
            *(u64*)&k_s[(r0 + i) * KS + 32 + 2 * tx] = pack2(s[i][2], s[i][3]);
        }
        __syncthreads();

        // O += P @ V  (dims d -> {2tx, 2tx+1, 32+2tx, 33+2tx})
        #pragma unroll 4
        for (int j = 0; j < 64; j++) {
            u64 v0 = *(const u64*)&v_s[j * VS + 2 * tx];
            u64 v1 = *(const u64*)&v_s[j * VS + 32 + 2 * tx];
            #pragma unroll
            for (int i = 0; i < 4; i++) {
                u64 p2 = dup2(k_s[(r0 + i) * KS + j]);
                fma2(acc[i][0], p2, v0);
                fma2(acc[i][1], p2, v1);
            }
        }
    }

    // Epilogue: normalize, write [n, h*DH + d]
    #pragma unroll
    for (int i = 0; i < 4; i++) {
        u64 iv = dup2(1.f / l[i]);
        mul2(acc[i][0], iv);
        mul2(acc[i][1], iv);
        float* ob = g_attn + (size_t)(i0 + r0 + i) * D_MODEL + h * DH;
        *(u64*)&ob[2 * tx]      = acc[i][0];
        *(u64*)&ob[32 + 2 * tx] = acc[i][1];
    }
}

// ---------------------------------------------------------------------------
// kernel_launch
// Output layout: [out (4096x1024) | new_k (16x4096x64) | new_v (16x4096x64)]
// ---------------------------------------------------------------------------
extern "C" void kernel_launch(void* const* d_in, const int* in_sizes, int n_in,
                              void* d_out, int out_size) {
    const float* x     = (const float*)d_in[0];
    const float* w_qkv = (const float*)d_in[1];
    const float* w_out = (const float*)d_in[2];
    const float* ln_g  = (const float*)d_in[3];
    const float* ln_b  = (const float*)d_in[4];
    float* out = (float*)d_out;

    float *p_h, *p_qkv, *p_attn;
    cudaGetSymbolAddress((void**)&p_h,    g_h);
    cudaGetSymbolAddress((void**)&p_qkv,  g_qkv);
    cudaGetSymbolAddress((void**)&p_attn, g_attn);

    // 1. LayerNorm
    ln_kernel<<<N_TOK, 256>>>(x, ln_g, ln_b);

    // 2. QKV projection: [4096,1024] @ [1024,3072]
    gemm128<<<dim3(QKV_COLS / 128, N_TOK / 128), 256>>>(p_h, w_qkv, p_qkv,
                                                        N_TOK, QKV_COLS, D_MODEL);

    // 3. Cache copies (pre-RoPE k, v)
    {
        int tot = 2 * HEADS * N_TOK * DH;
        copy_kv_kernel<<<(tot + 255) / 256, 256>>>(out);
    }

    // 4. RoPE on q and k (in place)
    {
        int tot = N_TOK * 1024;
        rope_kernel<<<(tot + 255) / 256, 256>>>();
    }

    // 5. Causal flash attention
    {
        static const int SMEM = (64 * QS + 64 * KS + 64 * VS) * (int)sizeof(float);
        cudaFuncSetAttribute(flash_kernel,
                             cudaFuncAttributeMaxDynamicSharedMemorySize, SMEM);
        flash_kernel<<<dim3(N_TOK / 64, HEADS), 256, SMEM>>>();
    }

    // 6. Output projection: [4096,1024] @ [1024,1024]
    gemm128<<<dim3(D_MODEL / 128, N_TOK / 128), 256>>>(p_attn, w_out, out,
                                                       N_TOK, D_MODEL, D_MODEL);
    (void)in_sizes; (void)n_in; (void)out_size;
}

// round 3
// speedup vs baseline: 1.5901x; 1.3123x over previous
#include <cuda_runtime.h>
#include <cuda_bf16.h>
#include <math.h>

// Problem constants
#define N_TOK   4096
#define D_MODEL 1024
#define HEADS   16
#define DH      64
#define QKV_COLS 3072   // 3 * inner, inner = HEADS*DH = 1024

// Scratch (allocation-free rule: __device__ globals)
__device__ float g_h[N_TOK * D_MODEL];       // LayerNorm output
__device__ float g_qkv[N_TOK * QKV_COLS];    // QKV projection / RoPE'd
__device__ float g_attn[N_TOK * D_MODEL];    // attention output

// ---- bf16 split helpers -----------------------------------------------------
__device__ __forceinline__ unsigned pk2(float a, float b) {
    __nv_bfloat162 t = __floats2bfloat162_rn(a, b);   // .x = a (low half)
    return *reinterpret_cast<unsigned*>(&t);
}
__device__ __forceinline__ float bflo(float x) {      // residual after bf16 hi
    return x - __bfloat162float(__float2bfloat16(x));
}

// mma.sync m16n8k16 bf16, fp32 accumulate (D == C)
__device__ __forceinline__ void mma_bf16(float c[4], const unsigned a[4],
                                         const unsigned b[2]) {
    asm volatile(
        "mma.sync.aligned.m16n8k16.row.col.f32.bf16.bf16.f32 "
        "{%0,%1,%2,%3}, {%4,%5,%6,%7}, {%8,%9}, {%0,%1,%2,%3};\n"
        : "+f"(c[0]), "+f"(c[1]), "+f"(c[2]), "+f"(c[3])
        : "r"(a[0]), "r"(a[1]), "r"(a[2]), "r"(a[3]), "r"(b[0]), "r"(b[1]));
}

// ---------------------------------------------------------------------------
// LayerNorm: one block per row (1024 elems, 256 threads)
// ---------------------------------------------------------------------------
__global__ void ln_kernel(const float* __restrict__ x,
                          const float* __restrict__ g,
                          const float* __restrict__ b) {
    int row = blockIdx.x;
    const float* xr = x + (size_t)row * D_MODEL;
    float s = 0.f, s2 = 0.f;
    for (int i = threadIdx.x; i < D_MODEL; i += 256) {
        float v = xr[i];
        s += v; s2 += v * v;
    }
    #pragma unroll
    for (int o = 16; o; o >>= 1) {
        s  += __shfl_xor_sync(0xffffffffu, s,  o);
        s2 += __shfl_xor_sync(0xffffffffu, s2, o);
    }
    __shared__ float ws[8], ws2[8];
    __shared__ float mu_s, inv_s;
    int wid = threadIdx.x >> 5, lane = threadIdx.x & 31;
    if (lane == 0) { ws[wid] = s; ws2[wid] = s2; }
    __syncthreads();
    if (threadIdx.x == 0) {
        float S = 0.f, S2 = 0.f;
        #pragma unroll
        for (int i = 0; i < 8; i++) { S += ws[i]; S2 += ws2[i]; }
        float mu  = S  * (1.f / D_MODEL);
        float var = S2 * (1.f / D_MODEL) - mu * mu;
        mu_s  = mu;
        inv_s = rsqrtf(var + 1e-5f);
    }
    __syncthreads();
    float mu = mu_s, inv = inv_s;
    float* yr = g_h + (size_t)row * D_MODEL;
    for (int i = threadIdx.x; i < D_MODEL; i += 256)
        yr[i] = (xr[i] - mu) * inv * g[i] + b[i];
}

// ---------------------------------------------------------------------------
// bf16x3 tensor-core GEMM: C[M,N] = A[M,K] @ B[K,N], fp32 in/out.
// BM=128, BN=128, BK=32, 256 threads = 8 warps (2m x 4n), warp tile 64x32.
// A split hi/lo staged [m][k] (u32-packed pairs), B staged transposed [n][k].
// Per k16 step, 3 MMAs per (m16,n8) tile: AhBh + AhBl + AlBh.
// ---------------------------------------------------------------------------
#define GKP 40    // bf16 k-stride (32 + 8 pad) -> 20 u32
#define GKPU 20

__global__ __launch_bounds__(256, 2)
void gemm_mma(const float* __restrict__ A, const float* __restrict__ B,
              float* __restrict__ C, int M, int N, int K) {
    extern __shared__ char smraw[];
    __nv_bfloat16* Ah = (__nv_bfloat16*)smraw;           // 128*40
    __nv_bfloat16* Al = Ah + 128 * GKP;
    __nv_bfloat16* Bh = Al + 128 * GKP;                  // [n][k]
    __nv_bfloat16* Bl = Bh + 128 * GKP;
    unsigned* Ahu = (unsigned*)Ah;
    unsigned* Alu = (unsigned*)Al;
    unsigned* Bhu = (unsigned*)Bh;
    unsigned* Blu = (unsigned*)Bl;

    int bm = blockIdx.y * 128, bn = blockIdx.x * 128;
    int tid = threadIdx.x;
    int wid = tid >> 5, lane = tid & 31;
    int warp_m = wid >> 2, warp_n = wid & 3;
    int r = lane >> 2, q = lane & 3;

    int arow = tid >> 1, ac0 = (tid & 1) * 16;
    int bk = tid >> 3,  bn0 = (tid & 7) * 16;

    float acc[4][4][4];
    #pragma unroll
    for (int mt = 0; mt < 4; mt++)
        #pragma unroll
        for (int nt = 0; nt < 4; nt++)
            #pragma unroll
            for (int e = 0; e < 4; e++) acc[mt][nt][e] = 0.f;

    for (int k0 = 0; k0 < K; k0 += 32) {
        // ---- stage A (split hi/lo, packed pairs) ----
        const float* ap = A + (size_t)(bm + arow) * K + k0 + ac0;
        #pragma unroll
        for (int i = 0; i < 4; i++) {
            float4 v = *(const float4*)(ap + 4 * i);
            int u = arow * GKPU + (ac0 + 4 * i) / 2;
            Ahu[u]     = pk2(v.x, v.y);
            Ahu[u + 1] = pk2(v.z, v.w);
            Alu[u]     = pk2(bflo(v.x), bflo(v.y));
            Alu[u + 1] = pk2(bflo(v.z), bflo(v.w));
        }
        // ---- stage B transposed [n][k] ----
        const float* bp = B + (size_t)(k0 + bk) * N + bn + bn0;
        #pragma unroll
        for (int i = 0; i < 4; i++) {
            float4 v = *(const float4*)(bp + 4 * i);
            int nb = bn0 + 4 * i;
            Bh[(nb + 0) * GKP + bk] = __float2bfloat16(v.x);
            Bh[(nb + 1) * GKP + bk] = __float2bfloat16(v.y);
            Bh[(nb + 2) * GKP + bk] = __float2bfloat16(v.z);
            Bh[(nb + 3) * GKP + bk] = __float2bfloat16(v.w);
            Bl[(nb + 0) * GKP + bk] = __float2bfloat16(bflo(v.x));
            Bl[(nb + 1) * GKP + bk] = __float2bfloat16(bflo(v.y));
            Bl[(nb + 2) * GKP + bk] = __float2bfloat16(bflo(v.z));
            Bl[(nb + 3) * GKP + bk] = __float2bfloat16(bflo(v.w));
        }
        __syncthreads();

        #pragma unroll
        for (int ks = 0; ks < 2; ks++) {
            // preload B fragments for this warp's 4 n-tiles
            unsigned bh[4][2], bl[4][2];
            #pragma unroll
            for (int nt = 0; nt < 4; nt++) {
                int n = warp_n * 32 + nt * 8 + r;
                int bb = n * GKPU + ks * 8 + q;
                bh[nt][0] = Bhu[bb]; bh[nt][1] = Bhu[bb + 4];
                bl[nt][0] = Blu[bb]; bl[nt][1] = Blu[bb + 4];
            }
            #pragma unroll
            for (int mt = 0; mt < 4; mt++) {
                int m = warp_m * 64 + mt * 16 + r;
                int ab = m * GKPU + ks * 8 + q;
                unsigned ah[4], al[4];
                ah[0] = Ahu[ab];              ah[1] = Ahu[ab + 8 * GKPU];
                ah[2] = Ahu[ab + 4];          ah[3] = Ahu[ab + 8 * GKPU + 4];
                al[0] = Alu[ab];              al[1] = Alu[ab + 8 * GKPU];
                al[2] = Alu[ab + 4];          al[3] = Alu[ab + 8 * GKPU + 4];
                #pragma unroll
                for (int nt = 0; nt < 4; nt++) {
                    mma_bf16(acc[mt][nt], ah, bh[nt]);
                    mma_bf16(acc[mt][nt], ah, bl[nt]);
                    mma_bf16(acc[mt][nt], al, bh[nt]);
                }
            }
        }
        __syncthreads();
    }

    // epilogue
    #pragma unroll
    for (int mt = 0; mt < 4; mt++) {
        int row = bm + warp_m * 64 + mt * 16 + r;
        #pragma unroll
        for (int nt = 0; nt < 4; nt++) {
            int col = bn + warp_n * 32 + nt * 8 + 2 * q;
            float2 v0 = make_float2(acc[mt][nt][0], acc[mt][nt][1]);
            float2 v1 = make_float2(acc[mt][nt][2], acc[mt][nt][3]);
            *(float2*)&C[(size_t)row * N + col]       = v0;
            *(float2*)&C[(size_t)(row + 8) * N + col] = v1;
        }
    }
}

// ---------------------------------------------------------------------------
// Copy PRE-RoPE k, v into output cache slots: layout [2][H][N][DH] appended
// after the 4.19M-element attention output.
// ---------------------------------------------------------------------------
__global__ void copy_kv_kernel(float* __restrict__ out) {
    int idx = blockIdx.x * blockDim.x + threadIdx.x;
    const int TOT = 2 * HEADS * N_TOK * DH;
    if (idx >= TOT) return;
    int which = idx / (HEADS * N_TOK * DH);
    int rr  = idx - which * (HEADS * N_TOK * DH);
    int h   = rr / (N_TOK * DH);
    int rem = rr - h * (N_TOK * DH);
    int n   = rem / DH;
    int d   = rem - n * DH;
    out[(size_t)N_TOK * D_MODEL + idx] =
        g_qkv[(size_t)n * QKV_COLS + D_MODEL + which * D_MODEL + h * DH + d];
}

// ---------------------------------------------------------------------------
// Interleaved-pair RoPE, in-place on q (cols 0..1023) and k (1024..2047)
// ---------------------------------------------------------------------------
__global__ void rope_kernel() {
    int idx = blockIdx.x * blockDim.x + threadIdx.x;
    if (idx >= N_TOK * 1024) return;
    int n    = idx >> 10;
    int rem  = idx & 1023;
    int mat  = rem >> 9;
    int pair = rem & 511;
    int h  = pair >> 5;
    int pd = pair & 31;
    float inv = exp2f(-((float)(2 * pd) * (1.f / 64.f)) * 13.287712379549449f);
    float ang = (float)n * inv;
    float sn, cs;
    sincosf(ang, &sn, &cs);
    float* base = g_qkv + (size_t)n * QKV_COLS + mat * D_MODEL + h * DH + 2 * pd;
    float x0 = base[0], x1 = base[1];
    base[0] = x0 * cs - x1 * sn;
    base[1] = x1 * cs + x0 * sn;
}

// ---------------------------------------------------------------------------
// Tensor-core causal flash attention (bf16x3). Grid (64 q-tiles rev, 16 heads),
// 128 threads = 4 warps; warp w owns q-rows 16w..16w+15 (FA2 style).
// Q[64x64] and K[64x64] smem [row][dh] hi/lo, V smem transposed [dh][key].
// S and O accumulators in registers; P repacked in-register into A-fragments.
// ---------------------------------------------------------------------------
#define FS  72     // bf16 stride (64 + 8 pad)
#define FSU 36     // u32 stride

__global__ __launch_bounds__(128, 4) void flash_mma() {
    extern __shared__ char smraw[];
    __nv_bfloat16* Qh = (__nv_bfloat16*)smraw;    // [qrow][dh]
    __nv_bfloat16* Ql = Qh + 64 * FS;
    __nv_bfloat16* Kh = Ql + 64 * FS;             // [key][dh]
    __nv_bfloat16* Kl = Kh + 64 * FS;
    __nv_bfloat16* Vh = Kl + 64 * FS;             // [dh][key]
    __nv_bfloat16* Vl = Vh + 64 * FS;
    unsigned* Qhu = (unsigned*)Qh; unsigned* Qlu = (unsigned*)Ql;
    unsigned* Khu = (unsigned*)Kh; unsigned* Klu = (unsigned*)Kl;
    unsigned* Vhu = (unsigned*)Vh; unsigned* Vlu = (unsigned*)Vl;

    int qt = gridDim.x - 1 - blockIdx.x;     // heavy tiles first
    int h  = blockIdx.y;
    int i0 = qt * 64;
    int tid = threadIdx.x;
    int wid = tid >> 5, lane = tid & 31;
    int r = lane >> 2, q = lane & 3;
    int rbase = 16 * wid;

    // ---- stage Q (scaled by 1/8), split hi/lo ----
    {
        int row = tid >> 1, c0 = (tid & 1) * 32;
        const float* qp = g_qkv + (size_t)(i0 + row) * QKV_COLS + h * DH + c0;
        #pragma unroll
        for (int i = 0; i < 8; i++) {
            float4 v = *(const float4*)(qp + 4 * i);
            v.x *= 0.125f; v.y *= 0.125f; v.z *= 0.125f; v.w *= 0.125f;
            int u = row * FSU + (c0 + 4 * i) / 2;
            Qhu[u]     = pk2(v.x, v.y);
            Qhu[u + 1] = pk2(v.z, v.w);
            Qlu[u]     = pk2(bflo(v.x), bflo(v.y));
            Qlu[u + 1] = pk2(bflo(v.z), bflo(v.w));
        }
    }

    float accO[8][4];
    #pragma unroll
    for (int nt = 0; nt < 8; nt++)
        #pragma unroll
        for (int e = 0; e < 4; e++) accO[nt][e] = 0.f;
    float mrow0 = -1e30f, mrow1 = -1e30f, lrow0 = 0.f, lrow1 = 0.f;

    for (int kt = 0; kt <= qt; kt++) {
        __syncthreads();   // previous-iter K/V consumers done (covers Q on iter 0)
        // ---- stage K [key][dh] and V transposed [dh][key] ----
        {
            int row = tid >> 1, c0 = (tid & 1) * 32;
            const float* kp = g_qkv + (size_t)(kt * 64 + row) * QKV_COLS
                              + D_MODEL + h * DH + c0;
            const float* vp = kp + D_MODEL;
            #pragma unroll
            for (int i = 0; i < 8; i++) {
                float4 kv = *(const float4*)(kp + 4 * i);
                int u = row * FSU + (c0 + 4 * i) / 2;
                Khu[u]     = pk2(kv.x, kv.y);
                Khu[u + 1] = pk2(kv.z, kv.w);
                Klu[u]     = pk2(bflo(kv.x), bflo(kv.y));
                Klu[u + 1] = pk2(bflo(kv.z), bflo(kv.w));
                float4 vv = *(const float4*)(vp + 4 * i);
                int d = c0 + 4 * i;
                Vh[(d + 0) * FS + row] = __float2bfloat16(vv.x);
                Vh[(d + 1) * FS + row] = __float2bfloat16(vv.y);
                Vh[(d + 2) * FS + row] = __float2bfloat16(vv.z);
                Vh[(d + 3) * FS + row] = __float2bfloat16(vv.w);
                Vl[(d + 0) * FS + row] = __float2bfloat16(bflo(vv.x));
                Vl[(d + 1) * FS + row] = __float2bfloat16(bflo(vv.y));
                Vl[(d + 2) * FS + row] = __float2bfloat16(bflo(vv.z));
                Vl[(d + 3) * FS + row] = __float2bfloat16(bflo(vv.w));
            }
        }
        __syncthreads();

        // ---- S = Q K^T : warp rows rbase..rbase+15, all 64 keys ----
        float s[8][4];
        #pragma unroll
        for (int nt = 0; nt < 8; nt++)
            #pragma unroll
            for (int e = 0; e < 4; e++) s[nt][e] = 0.f;

        #pragma unroll
        for (int ks = 0; ks < 4; ks++) {          // dh in k16 chunks
            int ab = (rbase + r) * FSU + ks * 8 + q;
            unsigned ah[4], al[4];
            ah[0] = Qhu[ab];     ah[1] = Qhu[ab + 8 * FSU];
            ah[2] = Qhu[ab + 4]; ah[3] = Qhu[ab + 8 * FSU + 4];
            al[0] = Qlu[ab];     al[1] = Qlu[ab + 8 * FSU];
            al[2] = Qlu[ab + 4]; al[3] = Qlu[ab + 8 * FSU + 4];
            #pragma unroll
            for (int nt = 0; nt < 8; nt++) {
                int bb = (nt * 8 + r) * FSU + ks * 8 + q;
                unsigned bh[2] = { Khu[bb], Khu[bb + 4] };
                unsigned bl[2] = { Klu[bb], Klu[bb + 4] };
                mma_bf16(s[nt], ah, bh);
                mma_bf16(s[nt], ah, bl);
                mma_bf16(s[nt], al, bh);
            }
        }

        // ---- causal mask (diagonal tile only; local row/col compare) ----
        if (kt == qt) {
            int row0 = rbase + r, row1 = row0 + 8;
            #pragma unroll
            for (int nt = 0; nt < 8; nt++) {
                int gc = nt * 8 + 2 * q;
                if (gc     > row0) s[nt][0] = -1e30f;
                if (gc + 1 > row0) s[nt][1] = -1e30f;
                if (gc     > row1) s[nt][2] = -1e30f;
                if (gc + 1 > row1) s[nt][3] = -1e30f;
            }
        }

        // ---- online softmax (rows r and r+8 of this warp stripe) ----
        float mx0 = -1e30f, mx1 = -1e30f;
        #pragma unroll
        for (int nt = 0; nt < 8; nt++) {
            mx0 = fmaxf(mx0, fmaxf(s[nt][0], s[nt][1]));
            mx1 = fmaxf(mx1, fmaxf(s[nt][2], s[nt][3]));
        }
        mx0 = fmaxf(mx0, __shfl_xor_sync(0xffffffffu, mx0, 1));
        mx0 = fmaxf(mx0, __shfl_xor_sync(0xffffffffu, mx0, 2));
        mx1 = fmaxf(mx1, __shfl_xor_sync(0xffffffffu, mx1, 1));
        mx1 = fmaxf(mx1, __shfl_xor_sync(0xffffffffu, mx1, 2));

        float mn0 = fmaxf(mrow0, mx0), mn1 = fmaxf(mrow1, mx1);
        float cr0 = __expf(mrow0 - mn0), cr1 = __expf(mrow1 - mn1);
        lrow0 *= cr0; lrow1 *= cr1;
        #pragma unroll
        for (int nt = 0; nt < 8; nt++) {
            accO[nt][0] *= cr0; accO[nt][1] *= cr0;
            accO[nt][2] *= cr1; accO[nt][3] *= cr1;
        }
        float sm0 = 0.f, sm1 = 0.f;
        #pragma unroll
        for (int nt = 0; nt < 8; nt++) {
            s[nt][0] = __expf(s[nt][0] - mn0);
            s[nt][1] = __expf(s[nt][1] - mn0);
            s[nt][2] = __expf(s[nt][2] - mn1);
            s[nt][3] = __expf(s[nt][3] - mn1);
            sm0 += s[nt][0] + s[nt][1];
            sm1 += s[nt][2] + s[nt][3];
        }
        sm0 += __shfl_xor_sync(0xffffffffu, sm0, 1);
        sm0 += __shfl_xor_sync(0xffffffffu, sm0, 2);
        sm1 += __shfl_xor_sync(0xffffffffu, sm1, 1);
        sm1 += __shfl_xor_sync(0xffffffffu, sm1, 2);
        lrow0 += sm0; lrow1 += sm1;
        mrow0 = mn0;  mrow1 = mn1;

        // ---- O += P V : P repacked from S fragments (hi/lo split) ----
        #pragma unroll
        for (int g = 0; g < 4; g++) {             // keys in k16 chunks
            const float* t0 = s[2 * g];
            const float* t1 = s[2 * g + 1];
            unsigned pah[4], pal[4];
            pah[0] = pk2(t0[0], t0[1]);  pal[0] = pk2(bflo(t0[0]), bflo(t0[1]));
            pah[1] = pk2(t0[2], t0[3]);  pal[1] = pk2(bflo(t0[2]), bflo(t0[3]));
            pah[2] = pk2(t1[0], t1[1]);  pal[2] = pk2(bflo(t1[0]), bflo(t1[1]));
            pah[3] = pk2(t1[2], t1[3]);  pal[3] = pk2(bflo(t1[2]), bflo(t1[3]));
            #pragma unroll
            for (int nt = 0; nt < 8; nt++) {      // dh n8 tiles
                int bb = (nt * 8 + r) * FSU + g * 8 + q;
                unsigned bh[2] = { Vhu[bb], Vhu[bb + 4] };
                unsigned bl[2] = { Vlu[bb], Vlu[bb + 4] };
                mma_bf16(accO[nt], pah, bh);
                mma_bf16(accO[nt], pah, bl);
                mma_bf16(accO[nt], pal, bh);
            }
        }
    }

    // ---- epilogue ----
    float iv0 = 1.f / lrow0, iv1 = 1.f / lrow1;
    int row0 = i0 + rbase + r;
    #pragma unroll
    for (int nt = 0; nt < 8; nt++) {
        int col = h * DH + nt * 8 + 2 * q;
        float2 v0 = make_float2(accO[nt][0] * iv0, accO[nt][1] * iv0);
        float2 v1 = make_float2(accO[nt][2] * iv1, accO[nt][3] * iv1);
        *(float2*)&g_attn[(size_t)row0 * D_MODEL + col]       = v0;
        *(float2*)&g_attn[(size_t)(row0 + 8) * D_MODEL + col] = v1;
    }
}

// ---------------------------------------------------------------------------
// kernel_launch
// Output layout: [out (4096x1024) | new_k (16x4096x64) | new_v (16x4096x64)]
// ---------------------------------------------------------------------------
extern "C" void kernel_launch(void* const* d_in, const int* in_sizes, int n_in,
                              void* d_out, int out_size) {
    const float* x     = (const float*)d_in[0];
    const float* w_qkv = (const float*)d_in[1];
    const float* w_out = (const float*)d_in[2];
    const float* ln_g  = (const float*)d_in[3];
    const float* ln_b  = (const float*)d_in[4];
    float* out = (float*)d_out;

    float *p_h, *p_qkv, *p_attn;
    cudaGetSymbolAddress((void**)&p_h,    g_h);
    cudaGetSymbolAddress((void**)&p_qkv,  g_qkv);
    cudaGetSymbolAddress((void**)&p_attn, g_attn);

    const int GEMM_SMEM  = 4 * 128 * GKP * (int)sizeof(__nv_bfloat16); // 40960
    const int FLASH_SMEM = 6 * 64 * FS * (int)sizeof(__nv_bfloat16);   // 55296
    cudaFuncSetAttribute(flash_mma,
                         cudaFuncAttributeMaxDynamicSharedMemorySize, FLASH_SMEM);

    // 1. LayerNorm
    ln_kernel<<<N_TOK, 256>>>(x, ln_g, ln_b);

    // 2. QKV projection: [4096,1024] @ [1024,3072]
    gemm_mma<<<dim3(QKV_COLS / 128, N_TOK / 128), 256, GEMM_SMEM>>>(
        p_h, w_qkv, p_qkv, N_TOK, QKV_COLS, D_MODEL);

    // 3. Cache copies (pre-RoPE k, v)
    {
        int tot = 2 * HEADS * N_TOK * DH;
        copy_kv_kernel<<<(tot + 255) / 256, 256>>>(out);
    }

    // 4. RoPE on q and k (in place)
    {
        int tot = N_TOK * 1024;
        rope_kernel<<<(tot + 255) / 256, 256>>>();
    }

    // 5. Causal flash attention (tensor cores)
    flash_mma<<<dim3(N_TOK / 64, HEADS), 128, FLASH_SMEM>>>();

    // 6. Output projection: [4096,1024] @ [1024,1024]
    gemm_mma<<<dim3(D_MODEL / 128, N_TOK / 128), 256, GEMM_SMEM>>>(
        p_attn, w_out, out, N_TOK, D_MODEL, D_MODEL);

    (void)in_sizes; (void)n_in; (void)out_size;
}

// round 4
// speedup vs baseline: 1.5917x; 1.0010x over previous
#include <cuda_runtime.h>
#include <cuda_bf16.h>
#include <math.h>

// Problem constants
#define N_TOK   4096
#define D_MODEL 1024
#define HEADS   16
#define DH      64
#define QKV_COLS 3072   // 3 * inner, inner = HEADS*DH = 1024

// Scratch (allocation-free rule: __device__ globals)
__device__ float g_h[N_TOK * D_MODEL];       // LayerNorm output
__device__ float g_qkv[N_TOK * QKV_COLS];    // QKV projection / RoPE'd
__device__ float g_attn[N_TOK * D_MODEL];    // attention output

// ---- bf16 split helpers -----------------------------------------------------
__device__ __forceinline__ unsigned pk2(float a, float b) {
    __nv_bfloat162 t = __floats2bfloat162_rn(a, b);   // .x = a (low half)
    return *reinterpret_cast<unsigned*>(&t);
}
__device__ __forceinline__ float bflo(float x) {      // residual after bf16 hi
    return x - __bfloat162float(__float2bfloat16(x));
}

// mma.sync m16n8k16 bf16, fp32 accumulate (D == C)
__device__ __forceinline__ void mma_bf16(float c[4], const unsigned a[4],
                                         const unsigned b[2]) {
    asm volatile(
        "mma.sync.aligned.m16n8k16.row.col.f32.bf16.bf16.f32 "
        "{%0,%1,%2,%3}, {%4,%5,%6,%7}, {%8,%9}, {%0,%1,%2,%3};\n"
        : "+f"(c[0]), "+f"(c[1]), "+f"(c[2]), "+f"(c[3])
        : "r"(a[0]), "r"(a[1]), "r"(a[2]), "r"(a[3]), "r"(b[0]), "r"(b[1]));
}

// ---------------------------------------------------------------------------
// LayerNorm: one block per row (1024 elems, 256 threads)
// ---------------------------------------------------------------------------
__global__ void ln_kernel(const float* __restrict__ x,
                          const float* __restrict__ g,
                          const float* __restrict__ b) {
    int row = blockIdx.x;
    const float* xr = x + (size_t)row * D_MODEL;
    float s = 0.f, s2 = 0.f;
    for (int i = threadIdx.x; i < D_MODEL; i += 256) {
        float v = xr[i];
        s += v; s2 += v * v;
    }
    #pragma unroll
    for (int o = 16; o; o >>= 1) {
        s  += __shfl_xor_sync(0xffffffffu, s,  o);
        s2 += __shfl_xor_sync(0xffffffffu, s2, o);
    }
    __shared__ float ws[8], ws2[8];
    __shared__ float mu_s, inv_s;
    int wid = threadIdx.x >> 5, lane = threadIdx.x & 31;
    if (lane == 0) { ws[wid] = s; ws2[wid] = s2; }
    __syncthreads();
    if (threadIdx.x == 0) {
        float S = 0.f, S2 = 0.f;
        #pragma unroll
        for (int i = 0; i < 8; i++) { S += ws[i]; S2 += ws2[i]; }
        float mu  = S  * (1.f / D_MODEL);
        float var = S2 * (1.f / D_MODEL) - mu * mu;
        mu_s  = mu;
        inv_s = rsqrtf(var + 1e-5f);
    }
    __syncthreads();
    float mu = mu_s, inv = inv_s;
    float* yr = g_h + (size_t)row * D_MODEL;
    for (int i = threadIdx.x; i < D_MODEL; i += 256)
        yr[i] = (xr[i] - mu) * inv * g[i] + b[i];
}

// ---------------------------------------------------------------------------
// bf16x3 tensor-core GEMM: C[M,N] = A[M,K] @ B[K,N], fp32 in/out.
// BM=128, BN=128, BK=32, 256 threads = 8 warps (2m x 4n), warp tile 64x32.
// A split hi/lo staged [m][k] (u32-packed pairs), B staged transposed [n][k].
// Per k16 step, 3 MMAs per (m16,n8) tile: AhBh + AhBl + AlBh.
// ---------------------------------------------------------------------------
#define GKP 40    // bf16 k-stride (32 + 8 pad) -> 20 u32
#define GKPU 20

__global__ __launch_bounds__(256, 2)
void gemm_mma(const float* __restrict__ A, const float* __restrict__ B,
              float* __restrict__ C, int M, int N, int K) {
    extern __shared__ char smraw[];
    __nv_bfloat16* Ah = (__nv_bfloat16*)smraw;           // 128*40
    __nv_bfloat16* Al = Ah + 128 * GKP;
    __nv_bfloat16* Bh = Al + 128 * GKP;                  // [n][k]
    __nv_bfloat16* Bl = Bh + 128 * GKP;
    unsigned* Ahu = (unsigned*)Ah;
    unsigned* Alu = (unsigned*)Al;
    unsigned* Bhu = (unsigned*)Bh;
    unsigned* Blu = (unsigned*)Bl;

    int bm = blockIdx.y * 128, bn = blockIdx.x * 128;
    int tid = threadIdx.x;
    int wid = tid >> 5, lane = tid & 31;
    int warp_m = wid >> 2, warp_n = wid & 3;
    int r = lane >> 2, q = lane & 3;

    int arow = tid >> 1, ac0 = (tid & 1) * 16;
    int bk = tid >> 3,  bn0 = (tid & 7) * 16;

    float acc[4][4][4];
    #pragma unroll
    for (int mt = 0; mt < 4; mt++)
        #pragma unroll
        for (int nt = 0; nt < 4; nt++)
            #pragma unroll
            for (int e = 0; e < 4; e++) acc[mt][nt][e] = 0.f;

    for (int k0 = 0; k0 < K; k0 += 32) {
        // ---- stage A (split hi/lo, packed pairs) ----
        const float* ap = A + (size_t)(bm + arow) * K + k0 + ac0;
        #pragma unroll
        for (int i = 0; i < 4; i++) {
            float4 v = *(const float4*)(ap + 4 * i);
            int u = arow * GKPU + (ac0 + 4 * i) / 2;
            Ahu[u]     = pk2(v.x, v.y);
            Ahu[u + 1] = pk2(v.z, v.w);
            Alu[u]     = pk2(bflo(v.x), bflo(v.y));
            Alu[u + 1] = pk2(bflo(v.z), bflo(v.w));
        }
        // ---- stage B transposed [n][k] ----
        const float* bp = B + (size_t)(k0 + bk) * N + bn + bn0;
        #pragma unroll
        for (int i = 0; i < 4; i++) {
            float4 v = *(const float4*)(bp + 4 * i);
            int nb = bn0 + 4 * i;
            Bh[(nb + 0) * GKP + bk] = __float2bfloat16(v.x);
            Bh[(nb + 1) * GKP + bk] = __float2bfloat16(v.y);
            Bh[(nb + 2) * GKP + bk] = __float2bfloat16(v.z);
            Bh[(nb + 3) * GKP + bk] = __float2bfloat16(v.w);
            Bl[(nb + 0) * GKP + bk] = __float2bfloat16(bflo(v.x));
            Bl[(nb + 1) * GKP + bk] = __float2bfloat16(bflo(v.y));
            Bl[(nb + 2) * GKP + bk] = __float2bfloat16(bflo(v.z));
            Bl[(nb + 3) * GKP + bk] = __float2bfloat16(bflo(v.w));
        }
        __syncthreads();

        #pragma unroll
        for (int ks = 0; ks < 2; ks++) {
            // preload B fragments for this warp's 4 n-tiles
            unsigned bh[4][2], bl[4][2];
            #pragma unroll
            for (int nt = 0; nt < 4; nt++) {
                int n = warp_n * 32 + nt * 8 + r;
                int bb = n * GKPU + ks * 8 + q;
                bh[nt][0] = Bhu[bb]; bh[nt][1] = Bhu[bb + 4];
                bl[nt][0] = Blu[bb]; bl[nt][1] = Blu[bb + 4];
            }
            #pragma unroll
            for (int mt = 0; mt < 4; mt++) {
                int m = warp_m * 64 + mt * 16 + r;
                int ab = m * GKPU + ks * 8 + q;
                unsigned ah[4], al[4];
                ah[0] = Ahu[ab];              ah[1] = Ahu[ab + 8 * GKPU];
                ah[2] = Ahu[ab + 4];          ah[3] = Ahu[ab + 8 * GKPU + 4];
                al[0] = Alu[ab];              al[1] = Alu[ab + 8 * GKPU];
                al[2] = Alu[ab + 4];          al[3] = Alu[ab + 8 * GKPU + 4];
                #pragma unroll
                for (int nt = 0; nt < 4; nt++) {
                    mma_bf16(acc[mt][nt], ah, bh[nt]);
                    mma_bf16(acc[mt][nt], ah, bl[nt]);
                    mma_bf16(acc[mt][nt], al, bh[nt]);
                }
            }
        }
        __syncthreads();
    }

    // epilogue
    #pragma unroll
    for (int mt = 0; mt < 4; mt++) {
        int row = bm + warp_m * 64 + mt * 16 + r;
        #pragma unroll
        for (int nt = 0; nt < 4; nt++) {
            int col = bn + warp_n * 32 + nt * 8 + 2 * q;
            float2 v0 = make_float2(acc[mt][nt][0], acc[mt][nt][1]);
            float2 v1 = make_float2(acc[mt][nt][2], acc[mt][nt][3]);
            *(float2*)&C[(size_t)row * N + col]       = v0;
            *(float2*)&C[(size_t)(row + 8) * N + col] = v1;
        }
    }
}

// ---------------------------------------------------------------------------
// Copy PRE-RoPE k, v into output cache slots: layout [2][H][N][DH] appended
// after the 4.19M-element attention output.
// ---------------------------------------------------------------------------
__global__ void copy_kv_kernel(float* __restrict__ out) {
    int idx = blockIdx.x * blockDim.x + threadIdx.x;
    const int TOT = 2 * HEADS * N_TOK * DH;
    if (idx >= TOT) return;
    int which = idx / (HEADS * N_TOK * DH);
    int rr  = idx - which * (HEADS * N_TOK * DH);
    int h   = rr / (N_TOK * DH);
    int rem = rr - h * (N_TOK * DH);
    int n   = rem / DH;
    int d   = rem - n * DH;
    out[(size_t)N_TOK * D_MODEL + idx] =
        g_qkv[(size_t)n * QKV_COLS + D_MODEL + which * D_MODEL + h * DH + d];
}

// ---------------------------------------------------------------------------
// Interleaved-pair RoPE, in-place on q (cols 0..1023) and k (1024..2047)
// ---------------------------------------------------------------------------
__global__ void rope_kernel() {
    int idx = blockIdx.x * blockDim.x + threadIdx.x;
    if (idx >= N_TOK * 1024) return;
    int n    = idx >> 10;
    int rem  = idx & 1023;
    int mat  = rem >> 9;
    int pair = rem & 511;
    int h  = pair >> 5;
    int pd = pair & 31;
    float inv = exp2f(-((float)(2 * pd) * (1.f / 64.f)) * 13.287712379549449f);
    float ang = (float)n * inv;
    float sn, cs;
    sincosf(ang, &sn, &cs);
    float* base = g_qkv + (size_t)n * QKV_COLS + mat * D_MODEL + h * DH + 2 * pd;
    float x0 = base[0], x1 = base[1];
    base[0] = x0 * cs - x1 * sn;
    base[1] = x1 * cs + x0 * sn;
}

// ---------------------------------------------------------------------------
// Tensor-core causal flash attention (bf16x3). Grid (64 q-tiles rev, 16 heads),
// 128 threads = 4 warps; warp w owns q-rows 16w..16w+15 (FA2 style).
// Q[64x64] and K[64x64] smem [row][dh] hi/lo, V smem transposed [dh][key].
// S and O accumulators in registers; P repacked in-register into A-fragments.
// ---------------------------------------------------------------------------
#define FS  72     // bf16 stride (64 + 8 pad)
#define FSU 36     // u32 stride

__global__ __launch_bounds__(128, 4) void flash_mma() {
    extern __shared__ char smraw[];
    __nv_bfloat16* Qh = (__nv_bfloat16*)smraw;    // [qrow][dh]
    __nv_bfloat16* Ql = Qh + 64 * FS;
    __nv_bfloat16* Kh = Ql + 64 * FS;             // [key][dh]
    __nv_bfloat16* Kl = Kh + 64 * FS;
    __nv_bfloat16* Vh = Kl + 64 * FS;             // [dh][key]
    __nv_bfloat16* Vl = Vh + 64 * FS;
    unsigned* Qhu = (unsigned*)Qh; unsigned* Qlu = (unsigned*)Ql;
    unsigned* Khu = (unsigned*)Kh; unsigned* Klu = (unsigned*)Kl;
    unsigned* Vhu = (unsigned*)Vh; unsigned* Vlu = (unsigned*)Vl;

    int qt = gridDim.x - 1 - blockIdx.x;     // heavy tiles first
    int h  = blockIdx.y;
    int i0 = qt * 64;
    int tid = threadIdx.x;
    int wid = tid >> 5, lane = tid & 31;
    int r = lane >> 2, q = lane & 3;
    int rbase = 16 * wid;

    // ---- stage Q (scaled by 1/8), split hi/lo ----
    {
        int row = tid >> 1, c0 = (tid & 1) * 32;
        const float* qp = g_qkv + (size_t)(i0 + row) * QKV_COLS + h * DH + c0;
        #pragma unroll
        for (int i = 0; i < 8; i++) {
            float4 v = *(const float4*)(qp + 4 * i);
            v.x *= 0.125f; v.y *= 0.125f; v.z *= 0.125f; v.w *= 0.125f;
            int u = row * FSU + (c0 + 4 * i) / 2;
            Qhu[u]     = pk2(v.x, v.y);
            Qhu[u + 1] = pk2(v.z, v.w);
            Qlu[u]     = pk2(bflo(v.x), bflo(v.y));
            Qlu[u + 1] = pk2(bflo(v.z), bflo(v.w));
        }
    }

    float accO[8][4];
    #pragma unroll
    for (int nt = 0; nt < 8; nt++)
        #pragma unroll
        for (int e = 0; e < 4; e++) accO[nt][e] = 0.f;
    float mrow0 = -1e30f, mrow1 = -1e30f, lrow0 = 0.f, lrow1 = 0.f;

    for (int kt = 0; kt <= qt; kt++) {
        __syncthreads();   // previous-iter K/V consumers done (covers Q on iter 0)
        // ---- stage K [key][dh] and V transposed [dh][key] ----
        {
            int row = tid >> 1, c0 = (tid & 1) * 32;
            const float* kp = g_qkv + (size_t)(kt * 64 + row) * QKV_COLS
                              + D_MODEL + h * DH + c0;
            const float* vp = kp + D_MODEL;
            #pragma unroll
            for (int i = 0; i < 8; i++) {
                float4 kv = *(const float4*)(kp + 4 * i);
                int u = row * FSU + (c0 + 4 * i) / 2;
                Khu[u]     = pk2(kv.x, kv.y);
                Khu[u + 1] = pk2(kv.z, kv.w);
                Klu[u]     = pk2(bflo(kv.x), bflo(kv.y));
                Klu[u + 1] = pk2(bflo(kv.z), bflo(kv.w));
                float4 vv = *(const float4*)(vp + 4 * i);
                int d = c0 + 4 * i;
                Vh[(d + 0) * FS + row] = __float2bfloat16(vv.x);
                Vh[(d + 1) * FS + row] = __float2bfloat16(vv.y);
                Vh[(d + 2) * FS + row] = __float2bfloat16(vv.z);
                Vh[(d + 3) * FS + row] = __float2bfloat16(vv.w);
                Vl[(d + 0) * FS + row] = __float2bfloat16(bflo(vv.x));
                Vl[(d + 1) * FS + row] = __float2bfloat16(bflo(vv.y));
                Vl[(d + 2) * FS + row] = __float2bfloat16(bflo(vv.z));
                Vl[(d + 3) * FS + row] = __float2bfloat16(bflo(vv.w));
            }
        }
        __syncthreads();

        // ---- S = Q K^T : warp rows rbase..rbase+15, all 64 keys ----
        float s[8][4];
        #pragma unroll
        for (int nt = 0; nt < 8; nt++)
            #pragma unroll
            for (int e = 0; e < 4; e++) s[nt][e] = 0.f;

        #pragma unroll
        for (int ks = 0; ks < 4; ks++) {          // dh in k16 chunks
            int ab = (rbase + r) * FSU + ks * 8 + q;
            unsigned ah[4], al[4];
            ah[0] = Qhu[ab];     ah[1] = Qhu[ab + 8 * FSU];
            ah[2] = Qhu[ab + 4]; ah[3] = Qhu[ab + 8 * FSU + 4];
            al[0] = Qlu[ab];     al[1] = Qlu[ab + 8 * FSU];
            al[2] = Qlu[ab + 4]; al[3] = Qlu[ab + 8 * FSU + 4];
            #pragma unroll
            for (int nt = 0; nt < 8; nt++) {
                int bb = (nt * 8 + r) * FSU + ks * 8 + q;
                unsigned bh[2] = { Khu[bb], Khu[bb + 4] };
                unsigned bl[2] = { Klu[bb], Klu[bb + 4] };
                mma_bf16(s[nt], ah, bh);
                mma_bf16(s[nt], ah, bl);
                mma_bf16(s[nt], al, bh);
            }
        }

        // ---- causal mask (diagonal tile only; local row/col compare) ----
        if (kt == qt) {
            int row0 = rbase + r, row1 = row0 + 8;
            #pragma unroll
            for (int nt = 0; nt < 8; nt++) {
                int gc = nt * 8 + 2 * q;
                if (gc     > row0) s[nt][0] = -1e30f;
                if (gc + 1 > row0) s[nt][1] = -1e30f;
                if (gc     > row1) s[nt][2] = -1e30f;
                if (gc + 1 > row1) s[nt][3] = -1e30f;
            }
        }

        // ---- online softmax (rows r and r+8 of this warp stripe) ----
        float mx0 = -1e30f, mx1 = -1e30f;
        #pragma unroll
        for (int nt = 0; nt < 8; nt++) {
            mx0 = fmaxf(mx0, fmaxf(s[nt][0], s[nt][1]));
            mx1 = fmaxf(mx1, fmaxf(s[nt][2], s[nt][3]));
        }
        mx0 = fmaxf(mx0, __shfl_xor_sync(0xffffffffu, mx0, 1));
        mx0 = fmaxf(mx0, __shfl_xor_sync(0xffffffffu, mx0, 2));
        mx1 = fmaxf(mx1, __shfl_xor_sync(0xffffffffu, mx1, 1));
        mx1 = fmaxf(mx1, __shfl_xor_sync(0xffffffffu, mx1, 2));

        float mn0 = fmaxf(mrow0, mx0), mn1 = fmaxf(mrow1, mx1);
        float cr0 = __expf(mrow0 - mn0), cr1 = __expf(mrow1 - mn1);
        lrow0 *= cr0; lrow1 *= cr1;
        #pragma unroll
        for (int nt = 0; nt < 8; nt++) {
            accO[nt][0] *= cr0; accO[nt][1] *= cr0;
            accO[nt][2] *= cr1; accO[nt][3] *= cr1;
        }
        float sm0 = 0.f, sm1 = 0.f;
        #pragma unroll
        for (int nt = 0; nt < 8; nt++) {
            s[nt][0] = __expf(s[nt][0] - mn0);
            s[nt][1] = __expf(s[nt][1] - mn0);
            s[nt][2] = __expf(s[nt][2] - mn1);
            s[nt][3] = __expf(s[nt][3] - mn1);
            sm0 += s[nt][0] + s[nt][1];
            sm1 += s[nt][2] + s[nt][3];
        }
        sm0 += __shfl_xor_sync(0xffffffffu, sm0, 1);
        sm0 += __shfl_xor_sync(0xffffffffu, sm0, 2);
        sm1 += __shfl_xor_sync(0xffffffffu, sm1, 1);
        sm1 += __shfl_xor_sync(0xffffffffu, sm1, 2);
        lrow0 += sm0; lrow1 += sm1;
        mrow0 = mn0;  mrow1 = mn1;

        // ---- O += P V : P repacked from S fragments (hi/lo split) ----
        #pragma unroll
        for (int g = 0; g < 4; g++) {             // keys in k16 chunks
            const float* t0 = s[2 * g];
            const float* t1 = s[2 * g + 1];
            unsigned pah[4], pal[4];
            pah[0] = pk2(t0[0], t0[1]);  pal[0] = pk2(bflo(t0[0]), bflo(t0[1]));
            pah[1] = pk2(t0[2], t0[3]);  pal[1] = pk2(bflo(t0[2]), bflo(t0[3]));
            pah[2] = pk2(t1[0], t1[1]);  pal[2] = pk2(bflo(t1[0]), bflo(t1[1]));
            pah[3] = pk2(t1[2], t1[3]);  pal[3] = pk2(bflo(t1[2]), bflo(t1[3]));
            #pragma unroll
            for (int nt = 0; nt < 8; nt++) {      // dh n8 tiles
                int bb = (nt * 8 + r) * FSU + g * 8 + q;
                unsigned bh[2] = { Vhu[bb], Vhu[bb + 4] };
                unsigned bl[2] = { Vlu[bb], Vlu[bb + 4] };
                mma_bf16(accO[nt], pah, bh);
                mma_bf16(accO[nt], pah, bl);
                mma_bf16(accO[nt], pal, bh);
            }
        }
    }

    // ---- epilogue ----
    float iv0 = 1.f / lrow0, iv1 = 1.f / lrow1;
    int row0 = i0 + rbase + r;
    #pragma unroll
    for (int nt = 0; nt < 8; nt++) {
        int col = h * DH + nt * 8 + 2 * q;
        float2 v0 = make_float2(accO[nt][0] * iv0, accO[nt][1] * iv0);
        float2 v1 = make_float2(accO[nt][2] * iv1, accO[nt][3] * iv1);
        *(float2*)&g_attn[(size_t)row0 * D_MODEL + col]       = v0;
        *(float2*)&g_attn[(size_t)(row0 + 8) * D_MODEL + col] = v1;
    }
}

// ---------------------------------------------------------------------------
// kernel_launch
// Output layout: [out (4096x1024) | new_k (16x4096x64) | new_v (16x4096x64)]
// ---------------------------------------------------------------------------
extern "C" void kernel_launch(void* const* d_in, const int* in_sizes, int n_in,
                              void* d_out, int out_size) {
    const float* x     = (const float*)d_in[0];
    const float* w_qkv = (const float*)d_in[1];
    const float* w_out = (const float*)d_in[2];
    const float* ln_g  = (const float*)d_in[3];
    const float* ln_b  = (const float*)d_in[4];
    float* out = (float*)d_out;

    float *p_h, *p_qkv, *p_attn;
    cudaGetSymbolAddress((void**)&p_h,    g_h);
    cudaGetSymbolAddress((void**)&p_qkv,  g_qkv);
    cudaGetSymbolAddress((void**)&p_attn, g_attn);

    const int GEMM_SMEM  = 4 * 128 * GKP * (int)sizeof(__nv_bfloat16); // 40960
    const int FLASH_SMEM = 6 * 64 * FS * (int)sizeof(__nv_bfloat16);   // 55296
    cudaFuncSetAttribute(flash_mma,
                         cudaFuncAttributeMaxDynamicSharedMemorySize, FLASH_SMEM);

    // 1. LayerNorm
    ln_kernel<<<N_TOK, 256>>>(x, ln_g, ln_b);

    // 2. QKV projection: [4096,1024] @ [1024,3072]
    gemm_mma<<<dim3(QKV_COLS / 128, N_TOK / 128), 256, GEMM_SMEM>>>(
        p_h, w_qkv, p_qkv, N_TOK, QKV_COLS, D_MODEL);

    // 3. Cache copies (pre-RoPE k, v)
    {
        int tot = 2 * HEADS * N_TOK * DH;
        copy_kv_kernel<<<(tot + 255) / 256, 256>>>(out);
    }

    // 4. RoPE on q and k (in place)
    {
        int tot = N_TOK * 1024;
        rope_kernel<<<(tot + 255) / 256, 256>>>();
    }

    // 5. Causal flash attention (tensor cores)
    flash_mma<<<dim3(N_TOK / 64, HEADS), 128, FLASH_SMEM>>>();

    // 6. Output projection: [4096,1024] @ [1024,1024]
    gemm_mma<<<dim3(D_MODEL / 128, N_TOK / 128), 256, GEMM_SMEM>>>(
        p_attn, w_out, out, N_TOK, D_MODEL, D_MODEL);

    (void)in_sizes; (void)n_in; (void)out_size;
}